// round 5
// baseline (speedup 1.0000x reference)
#include <cuda_runtime.h>
#include <cuda_fp16.h>
#include <cuda_fp8.h>

#define NN 8192
#define EPSI 0.1f
#define NITERS 50
#define NBLK 128          // blocks in fused kernel
#define RPB 64            // rows per block
#define BATCH 8           // rows per batch

// K = exp(M/eps) as e5m2 fp8 (range [1, 22026.5] fits; decode = byte<<8 == fp16). 64MB.
__device__ __align__(16) unsigned char dK8[(size_t)NN * NN];
__device__ float dU[NN];                              // true u of current iteration
__device__ __align__(16) __half dVh[(NITERS + 1) * NN];  // v*2^-8 per iteration
__device__ __align__(16) float dScr[NBLK][NN];        // per-block colAcc partials (x 2^31)
__device__ float dColAccLast[NN];                     // colAcc after last finalize
__device__ float dR[NN];                              // row sums of target
__device__ float dCs[NN];                             // col sums of target
__device__ float dDot;                                // sum(target * M)

__device__ __forceinline__ __half2 e5lo(unsigned int x) {
    unsigned int r = __byte_perm(x, 0u, 0x1404);      // -> half2{b0<<8, b1<<8}
    return *reinterpret_cast<__half2*>(&r);
}
__device__ __forceinline__ __half2 e5hi(unsigned int x) {
    unsigned int r = __byte_perm(x, 0u, 0x3424);      // -> half2{b2<<8, b3<<8}
    return *reinterpret_cast<__half2*>(&r);
}

__device__ __forceinline__ unsigned long long pol_last() {
    unsigned long long p;
    asm("createpolicy.fractional.L2::evict_last.b64 %0, 1.0;" : "=l"(p));
    return p;
}
__device__ __forceinline__ unsigned long long pol_first() {
    unsigned long long p;
    asm("createpolicy.fractional.L2::evict_first.b64 %0, 1.0;" : "=l"(p));
    return p;
}
__device__ __forceinline__ uint4 ldK(const unsigned char* p, unsigned long long pol) {
    uint4 v;
    asm volatile("ld.global.nc.L2::cache_hint.v4.u32 {%0,%1,%2,%3}, [%4], %5;"
                 : "=r"(v.x), "=r"(v.y), "=r"(v.z), "=r"(v.w) : "l"(p), "l"(pol));
    return v;
}
__device__ __forceinline__ void stK(unsigned char* p, uint2 v, unsigned long long pol) {
    asm volatile("st.global.L2::cache_hint.v2.u32 [%0], {%1,%2}, %3;"
                 :: "l"(p), "r"(v.x), "r"(v.y), "l"(pol) : "memory");
}
__device__ __forceinline__ float4 ldS(const float* p, unsigned long long pol) {
    float4 v;
    asm volatile("ld.global.nc.L2::cache_hint.v4.f32 {%0,%1,%2,%3}, [%4], %5;"
                 : "=f"(v.x), "=f"(v.y), "=f"(v.z), "=f"(v.w) : "l"(p), "l"(pol));
    return v;
}

__global__ void init_kernel() {
    int j = blockIdx.x * blockDim.x + threadIdx.x;
    if (j < NN) {
        dR[j] = 0.f;
        dCs[j] = 0.f;
        dVh[j] = __float2half(0.00390625f);           // v_0 = 1, stored *2^-8
    }
    if (j == 0) dDot = 0.f;
}

// One pass over M and target: build K (e5m2), row/col sums of target, dot(target, M).
__global__ void __launch_bounds__(256) prep_kernel(const float* __restrict__ M,
                                                   const float* __restrict__ T) {
    __shared__ float sred[8 * 256];
    __shared__ float sdot_s[256];
    const unsigned long long pF = pol_first();
    const unsigned long long pL = pol_last();
    const int w = threadIdx.x >> 5, l = threadIdx.x & 31;
    const int col0 = blockIdx.x * 256 + l * 8;
    const int r0 = blockIdx.y * 256;
    const float SC = 10.0f * 1.4426950408889634f;     // (1/eps) * log2(e)

    float cs[8];
#pragma unroll
    for (int k = 0; k < 8; k++) cs[k] = 0.f;
    float dot = 0.f;

    for (int r = r0 + w; r < r0 + 256; r += 8) {
        size_t base = (size_t)r * NN + col0;
        float4 m0 = ldS(M + base, pF);
        float4 m1 = ldS(M + base + 4, pF);
        float4 t0 = ldS(T + base, pF);
        float4 t1 = ldS(T + base + 4, pF);

        union { uint2 u; __nv_fp8x2_storage_t s[4]; } P;
        P.s[0] = __nv_cvt_float2_to_fp8x2(make_float2(exp2f(m0.x * SC), exp2f(m0.y * SC)),
                                          __NV_SATFINITE, __NV_E5M2);
        P.s[1] = __nv_cvt_float2_to_fp8x2(make_float2(exp2f(m0.z * SC), exp2f(m0.w * SC)),
                                          __NV_SATFINITE, __NV_E5M2);
        P.s[2] = __nv_cvt_float2_to_fp8x2(make_float2(exp2f(m1.x * SC), exp2f(m1.y * SC)),
                                          __NV_SATFINITE, __NV_E5M2);
        P.s[3] = __nv_cvt_float2_to_fp8x2(make_float2(exp2f(m1.z * SC), exp2f(m1.w * SC)),
                                          __NV_SATFINITE, __NV_E5M2);
        stK(dK8 + base, P.u, pL);

        cs[0] += t0.x; cs[1] += t0.y; cs[2] += t0.z; cs[3] += t0.w;
        cs[4] += t1.x; cs[5] += t1.y; cs[6] += t1.z; cs[7] += t1.w;

        dot += m0.x * t0.x + m0.y * t0.y + m0.z * t0.z + m0.w * t0.w
             + m1.x * t1.x + m1.y * t1.y + m1.z * t1.z + m1.w * t1.w;

        float rs = t0.x + t0.y + t0.z + t0.w + t1.x + t1.y + t1.z + t1.w;
#pragma unroll
        for (int o = 16; o > 0; o >>= 1) rs += __shfl_xor_sync(0xffffffffu, rs, o);
        if (l == 0) atomicAdd(&dR[r], rs);
    }

#pragma unroll
    for (int k = 0; k < 8; k++) sred[w * 256 + l * 8 + k] = cs[k];
    sdot_s[threadIdx.x] = dot;
    __syncthreads();

    float s = 0.f;
#pragma unroll
    for (int w2 = 0; w2 < 8; w2++) s += sred[w2 * 256 + threadIdx.x];
    atomicAdd(&dCs[blockIdx.x * 256 + threadIdx.x], s);

    for (int off = 128; off > 0; off >>= 1) {
        if (threadIdx.x < off) sdot_s[threadIdx.x] += sdot_s[threadIdx.x + off];
        __syncthreads();
    }
    if (threadIdx.x == 0) atomicAdd(&dDot, sdot_s[0]);
}

// Fused Sinkhorn half-iteration pair: ONE sweep over K computes
//   u_i = a_i / (K_i . v)      and      partial colAcc_j += K_ij * u_i
// Thread owns 16 fixed columns (one uint4 of each row). 128 blocks x 64 rows.
__global__ void __launch_bounds__(512, 1) fused_iter(const float* __restrict__ a, int iter) {
    __shared__ float sdot[BATCH][16];
    __shared__ __half su[BATCH];
    const unsigned long long pL = pol_last();
    const int t = threadIdx.x;
    const int c0 = t * 16;                            // this thread's column base
    const int r0 = blockIdx.x * RPB;

    // v (scaled 2^-8) for my 16 columns -> 8 half2 regs
    union { uint4 q[2]; __half2 h[8]; } V;
    const uint4* vp = reinterpret_cast<const uint4*>(dVh + (size_t)iter * NN + c0);
    V.q[0] = vp[0];
    V.q[1] = vp[1];

    float facc[16];
#pragma unroll
    for (int i = 0; i < 16; i++) facc[i] = 0.f;

    const unsigned char* base = dK8 + (size_t)r0 * NN + c0;
    uint4 kq[2][BATCH];
#pragma unroll
    for (int r = 0; r < BATCH; r++) kq[0][r] = ldK(base + (size_t)r * NN, pL);

    for (int bt = 0; bt < RPB / BATCH; bt++) {
        const int cur = bt & 1;
        if (bt < RPB / BATCH - 1) {
#pragma unroll
            for (int r = 0; r < BATCH; r++)
                kq[cur ^ 1][r] = ldK(base + (size_t)((bt + 1) * BATCH + r) * NN, pL);
        }

        // Phase A: per-row partial dot with v
        float dotp[BATCH];
#pragma unroll
        for (int r = 0; r < BATCH; r++) {
            uint4 kk = kq[cur][r];
            __half2 hs = __hmul2(e5lo(kk.x), V.h[0]);
            hs = __hfma2(e5hi(kk.x), V.h[1], hs);
            hs = __hfma2(e5lo(kk.y), V.h[2], hs);
            hs = __hfma2(e5hi(kk.y), V.h[3], hs);
            hs = __hfma2(e5lo(kk.z), V.h[4], hs);
            hs = __hfma2(e5hi(kk.z), V.h[5], hs);
            hs = __hfma2(e5lo(kk.w), V.h[6], hs);
            hs = __hfma2(e5hi(kk.w), V.h[7], hs);
            float2 f = __half22float2(hs);
            dotp[r] = f.x + f.y;
        }
#pragma unroll
        for (int r = 0; r < BATCH; r++) {
#pragma unroll
            for (int o = 16; o > 0; o >>= 1)
                dotp[r] += __shfl_xor_sync(0xffffffffu, dotp[r], o);
        }
        if ((t & 31) == 0) {
            int w = t >> 5;
#pragma unroll
            for (int r = 0; r < BATCH; r++) sdot[r][w] = dotp[r];
        }
        __syncthreads();

        if (t < 32) {
            int r = t >> 2, q = t & 3;
            float s = sdot[r][q * 4] + sdot[r][q * 4 + 1]
                    + sdot[r][q * 4 + 2] + sdot[r][q * 4 + 3];
            s += __shfl_xor_sync(0xffffffffu, s, 1);
            s += __shfl_xor_sync(0xffffffffu, s, 2);
            if (q == 0) {
                int row = r0 + bt * BATCH + r;
                float u = (a[row] * 0.00390625f) / s;   // dot was scaled 2^-8
                dU[row] = u;
                su[r] = __float2half(u * 2147483648.0f);  // * 2^31
            }
        }
        __syncthreads();

        // Phase B: colAcc partial += K * u (same registers, decode again)
        __half2 bacc[8];
#pragma unroll
        for (int i = 0; i < 8; i++) bacc[i] = __float2half2_rn(0.f);
#pragma unroll
        for (int r = 0; r < BATCH; r++) {
            __half2 uu = __half2half2(su[r]);
            uint4 kk = kq[cur][r];
            bacc[0] = __hfma2(e5lo(kk.x), uu, bacc[0]);
            bacc[1] = __hfma2(e5hi(kk.x), uu, bacc[1]);
            bacc[2] = __hfma2(e5lo(kk.y), uu, bacc[2]);
            bacc[3] = __hfma2(e5hi(kk.y), uu, bacc[3]);
            bacc[4] = __hfma2(e5lo(kk.z), uu, bacc[4]);
            bacc[5] = __hfma2(e5hi(kk.z), uu, bacc[5]);
            bacc[6] = __hfma2(e5lo(kk.w), uu, bacc[6]);
            bacc[7] = __hfma2(e5hi(kk.w), uu, bacc[7]);
        }
#pragma unroll
        for (int i = 0; i < 8; i++) {
            float2 f = __half22float2(bacc[i]);
            facc[2 * i]     += f.x;
            facc[2 * i + 1] += f.y;
        }
    }

    // write per-block partials (still scaled by 2^31)
    float4* sp = reinterpret_cast<float4*>(&dScr[blockIdx.x][c0]);
#pragma unroll
    for (int i = 0; i < 4; i++)
        sp[i] = make_float4(facc[4 * i], facc[4 * i + 1], facc[4 * i + 2], facc[4 * i + 3]);
}

// Sum the 128 per-block partials per column; produce colAcc and next v (half, *2^-8).
__global__ void __launch_bounds__(128) finalize_iter(const float* __restrict__ b, int iter) {
    const int c = blockIdx.x * 128 + threadIdx.x;
    float acc[16];
#pragma unroll
    for (int i = 0; i < 16; i++) acc[i] = 0.f;
#pragma unroll 2
    for (int p = 0; p < NBLK; p += 16) {
#pragma unroll
        for (int i = 0; i < 16; i++) acc[i] += dScr[p + i][c];
    }
    float tot = 0.f;
#pragma unroll
    for (int i = 0; i < 16; i++) tot += acc[i];
    tot *= (1.0f / 2147483648.0f);                    // undo 2^31 u scale
    dColAccLast[c] = tot;
    dVh[(size_t)(iter + 1) * NN + c] = __float2half(__fdividef(b[c], tot) * 0.00390625f);
}

// loss = -( dot(target,M)/eps + sum_i R_i ln u_i + sum_j C_j ln v_j )
__global__ void loss_kernel(const float* __restrict__ b, float* __restrict__ out) {
    __shared__ float sred[1024];
    float p = 0.f;
    for (int i = threadIdx.x; i < NN; i += 1024) {
        p += dR[i] * logf(dU[i]);
        p += dCs[i] * (logf(b[i]) - logf(dColAccLast[i]));
    }
    sred[threadIdx.x] = p;
    __syncthreads();
    for (int off = 512; off > 0; off >>= 1) {
        if (threadIdx.x < off) sred[threadIdx.x] += sred[threadIdx.x + off];
        __syncthreads();
    }
    if (threadIdx.x == 0) out[0] = -(sred[0] + dDot * (1.0f / EPSI));
}

extern "C" void kernel_launch(void* const* d_in, const int* in_sizes, int n_in,
                              void* d_out, int out_size) {
    const float* M = (const float*)d_in[0];
    const float* T = (const float*)d_in[1];
    const float* a = (const float*)d_in[2];
    const float* b = (const float*)d_in[3];
    float* out = (float*)d_out;

    init_kernel<<<(NN + 255) / 256, 256>>>();
    prep_kernel<<<dim3(32, 32), 256>>>(M, T);
    for (int k = 0; k < NITERS; k++) {
        fused_iter<<<NBLK, 512>>>(a, k);
        finalize_iter<<<NN / 128, 128>>>(b, k);
    }
    loss_kernel<<<1, 1024>>>(b, out);
}

// round 7
// speedup vs baseline: 1.7644x; 1.7644x over previous
#include <cuda_runtime.h>
#include <cuda_fp16.h>
#include <cuda_fp8.h>

#define NN 8192
#define EPSI 0.1f
#define NITERS 50
#define NBLK 148            // one block per SM
#define THREADS 512
#define BATCH 4             // rows per pipeline stage
#define STAGES 3
#define NBATCH 14           // max 56 rows per block = 14 batches (pad with u=0)
#define STAGE_BYTES (BATCH * NN)   // 32768
#define SMEMSZ (STAGES * STAGE_BYTES + 64 * 4 + 2 * 64 * 4)

// K = exp(M/eps) as e5m2 fp8 (range [1, 22026.5] fits; decode = byte<<8 == fp16). 64MB.
__device__ __align__(16) unsigned char dK8[(size_t)NN * NN];
__device__ float dU[NN];                                 // true u of current iteration
__device__ __align__(16) __half dVh[(NITERS + 1) * NN];  // v * 2^-8 per iteration
__device__ __align__(16) float dScr[NBLK][NN];           // per-block colAcc partials (x 2^31)
__device__ float dColAccLast[NN];
__device__ float dR[NN];                                 // row sums of target
__device__ float dCs[NN];                                // col sums of target
__device__ float dDot;                                   // sum(target * M)

__device__ __forceinline__ __half2 e5lo(unsigned int x) {
    unsigned int r = __byte_perm(x, 0u, 0x1404);
    return *reinterpret_cast<__half2*>(&r);
}
__device__ __forceinline__ __half2 e5hi(unsigned int x) {
    unsigned int r = __byte_perm(x, 0u, 0x3424);
    return *reinterpret_cast<__half2*>(&r);
}
__device__ __forceinline__ unsigned long long pol_last() {
    unsigned long long p;
    asm("createpolicy.fractional.L2::evict_last.b64 %0, 1.0;" : "=l"(p));
    return p;
}
__device__ __forceinline__ unsigned long long pol_first() {
    unsigned long long p;
    asm("createpolicy.fractional.L2::evict_first.b64 %0, 1.0;" : "=l"(p));
    return p;
}
__device__ __forceinline__ void stK(unsigned char* p, uint2 v, unsigned long long pol) {
    asm volatile("st.global.L2::cache_hint.v2.u32 [%0], {%1,%2}, %3;"
                 :: "l"(p), "r"(v.x), "r"(v.y), "l"(pol) : "memory");
}
__device__ __forceinline__ float4 ldS(const float* p, unsigned long long pol) {
    float4 v;
    asm volatile("ld.global.nc.L2::cache_hint.v4.f32 {%0,%1,%2,%3}, [%4], %5;"
                 : "=f"(v.x), "=f"(v.y), "=f"(v.z), "=f"(v.w) : "l"(p), "l"(pol));
    return v;
}
// plain cp.async (NO cache-hint policy — the hinted LDGSTS variant traps on sm_103a)
__device__ __forceinline__ void cpK(unsigned int dst, const unsigned char* src) {
    asm volatile("cp.async.cg.shared.global [%0], [%1], 16;"
                 :: "r"(dst), "l"(src) : "memory");
}

__global__ void init_kernel() {
    int j = blockIdx.x * blockDim.x + threadIdx.x;
    if (j < NN) {
        dR[j] = 0.f;
        dCs[j] = 0.f;
        dVh[j] = __float2half(0.00390625f);      // v_0 = 1, stored *2^-8
    }
    if (j == 0) dDot = 0.f;
}

// One pass over M and target: build K (e5m2), row/col sums of target, dot(target, M).
__global__ void __launch_bounds__(256) prep_kernel(const float* __restrict__ M,
                                                   const float* __restrict__ T) {
    __shared__ float sred[8 * 256];
    __shared__ float sdot_s[256];
    const unsigned long long pF = pol_first();
    const unsigned long long pL = pol_last();
    const int w = threadIdx.x >> 5, l = threadIdx.x & 31;
    const int col0 = blockIdx.x * 256 + l * 8;
    const int r0 = blockIdx.y * 256;
    const float SC = 10.0f * 1.4426950408889634f;

    float cs[8];
#pragma unroll
    for (int k = 0; k < 8; k++) cs[k] = 0.f;
    float dot = 0.f;

    for (int r = r0 + w; r < r0 + 256; r += 8) {
        size_t base = (size_t)r * NN + col0;
        float4 m0 = ldS(M + base, pF);
        float4 m1 = ldS(M + base + 4, pF);
        float4 t0 = ldS(T + base, pF);
        float4 t1 = ldS(T + base + 4, pF);

        union { uint2 u; __nv_fp8x2_storage_t s[4]; } P;
        P.s[0] = __nv_cvt_float2_to_fp8x2(make_float2(exp2f(m0.x * SC), exp2f(m0.y * SC)),
                                          __NV_SATFINITE, __NV_E5M2);
        P.s[1] = __nv_cvt_float2_to_fp8x2(make_float2(exp2f(m0.z * SC), exp2f(m0.w * SC)),
                                          __NV_SATFINITE, __NV_E5M2);
        P.s[2] = __nv_cvt_float2_to_fp8x2(make_float2(exp2f(m1.x * SC), exp2f(m1.y * SC)),
                                          __NV_SATFINITE, __NV_E5M2);
        P.s[3] = __nv_cvt_float2_to_fp8x2(make_float2(exp2f(m1.z * SC), exp2f(m1.w * SC)),
                                          __NV_SATFINITE, __NV_E5M2);
        stK(dK8 + base, P.u, pL);

        cs[0] += t0.x; cs[1] += t0.y; cs[2] += t0.z; cs[3] += t0.w;
        cs[4] += t1.x; cs[5] += t1.y; cs[6] += t1.z; cs[7] += t1.w;

        dot += m0.x * t0.x + m0.y * t0.y + m0.z * t0.z + m0.w * t0.w
             + m1.x * t1.x + m1.y * t1.y + m1.z * t1.z + m1.w * t1.w;

        float rs = t0.x + t0.y + t0.z + t0.w + t1.x + t1.y + t1.z + t1.w;
#pragma unroll
        for (int o = 16; o > 0; o >>= 1) rs += __shfl_xor_sync(0xffffffffu, rs, o);
        if (l == 0) atomicAdd(&dR[r], rs);
    }

#pragma unroll
    for (int k = 0; k < 8; k++) sred[w * 256 + l * 8 + k] = cs[k];
    sdot_s[threadIdx.x] = dot;
    __syncthreads();

    float s = 0.f;
#pragma unroll
    for (int w2 = 0; w2 < 8; w2++) s += sred[w2 * 256 + threadIdx.x];
    atomicAdd(&dCs[blockIdx.x * 256 + threadIdx.x], s);

    for (int off = 128; off > 0; off >>= 1) {
        if (threadIdx.x < off) sdot_s[threadIdx.x] += sdot_s[threadIdx.x + off];
        __syncthreads();
    }
    if (threadIdx.x == 0) atomicAdd(&dDot, sdot_s[0]);
}

// Fused Sinkhorn pair: one sweep over K computes u_i = a_i/(K_i.v) AND colAcc
// partials. 148 blocks (1/SM), 512 threads, thread owns 16 fixed columns.
// K staged through smem with a 3-deep cp.async pipeline (4 rows x 8KB per stage).
__global__ void __launch_bounds__(THREADS, 1)
fused_iter(const float* __restrict__ a, int iter) {
    extern __shared__ char smem[];
    float* sa   = reinterpret_cast<float*>(smem + STAGES * STAGE_BYTES);   // [64]
    float* sdot = sa + 64;                                                  // [2][64]
    const int t = threadIdx.x;
    const int l = t & 31;
    const int w = t >> 5;
    const int c0 = t * 16;
    const int bid = blockIdx.x;
    const int r0 = (bid * NN) / NBLK;
    const int r1 = ((bid + 1) * NN) / NBLK;   // 55 or 56 rows

    if (t < 64) {
        int rr = r0 + t;
        sa[t] = (rr < r1) ? a[rr] * 0.00390625f : 0.f;
    }

    union { uint4 q[2]; __half2 h[8]; } V;   // v*2^-8 for my 16 cols
    const uint4* vp = reinterpret_cast<const uint4*>(dVh + (size_t)iter * NN + c0);
    V.q[0] = vp[0];
    V.q[1] = vp[1];

    float facc[16];
#pragma unroll
    for (int i = 0; i < 16; i++) facc[i] = 0.f;

    // prologue: fill stages 0..2
#pragma unroll
    for (int s = 0; s < STAGES; s++) {
        int rb = r0 + s * BATCH;
#pragma unroll
        for (int r = 0; r < BATCH; r++) {
            int gr = rb + r; gr = (gr < r1) ? gr : (r1 - 1);
            unsigned int dst = (unsigned int)__cvta_generic_to_shared(
                smem + s * STAGE_BYTES + r * NN + c0);
            cpK(dst, dK8 + (size_t)gr * NN + c0);
        }
        asm volatile("cp.async.commit_group;" ::: "memory");
    }

#pragma unroll 1
    for (int bt = 0; bt < NBATCH; bt++) {
        asm volatile("cp.async.wait_group 2;" ::: "memory");
        const uint4* sp = reinterpret_cast<const uint4*>(
            smem + (bt % STAGES) * STAGE_BYTES) + t;
        uint4 kq0 = sp[0], kq1 = sp[512], kq2 = sp[1024], kq3 = sp[1536];

        // refill just-freed slot (data already in regs)
        int nb = bt + STAGES;
        if (nb < NBATCH) {
            int rb = r0 + nb * BATCH;
#pragma unroll
            for (int r = 0; r < BATCH; r++) {
                int gr = rb + r; gr = (gr < r1) ? gr : (r1 - 1);
                unsigned int dst = (unsigned int)__cvta_generic_to_shared(
                    smem + (nb % STAGES) * STAGE_BYTES + r * NN + c0);
                cpK(dst, dK8 + (size_t)gr * NN + c0);
            }
        }
        asm volatile("cp.async.commit_group;" ::: "memory");

        // Phase A: partial dots
        float dotp[4];
        {
            __half2 hs = __hmul2(e5lo(kq0.x), V.h[0]);
            hs = __hfma2(e5hi(kq0.x), V.h[1], hs); hs = __hfma2(e5lo(kq0.y), V.h[2], hs);
            hs = __hfma2(e5hi(kq0.y), V.h[3], hs); hs = __hfma2(e5lo(kq0.z), V.h[4], hs);
            hs = __hfma2(e5hi(kq0.z), V.h[5], hs); hs = __hfma2(e5lo(kq0.w), V.h[6], hs);
            hs = __hfma2(e5hi(kq0.w), V.h[7], hs);
            float2 f = __half22float2(hs); dotp[0] = f.x + f.y;
        }
        {
            __half2 hs = __hmul2(e5lo(kq1.x), V.h[0]);
            hs = __hfma2(e5hi(kq1.x), V.h[1], hs); hs = __hfma2(e5lo(kq1.y), V.h[2], hs);
            hs = __hfma2(e5hi(kq1.y), V.h[3], hs); hs = __hfma2(e5lo(kq1.z), V.h[4], hs);
            hs = __hfma2(e5hi(kq1.z), V.h[5], hs); hs = __hfma2(e5lo(kq1.w), V.h[6], hs);
            hs = __hfma2(e5hi(kq1.w), V.h[7], hs);
            float2 f = __half22float2(hs); dotp[1] = f.x + f.y;
        }
        {
            __half2 hs = __hmul2(e5lo(kq2.x), V.h[0]);
            hs = __hfma2(e5hi(kq2.x), V.h[1], hs); hs = __hfma2(e5lo(kq2.y), V.h[2], hs);
            hs = __hfma2(e5hi(kq2.y), V.h[3], hs); hs = __hfma2(e5lo(kq2.z), V.h[4], hs);
            hs = __hfma2(e5hi(kq2.z), V.h[5], hs); hs = __hfma2(e5lo(kq2.w), V.h[6], hs);
            hs = __hfma2(e5hi(kq2.w), V.h[7], hs);
            float2 f = __half22float2(hs); dotp[2] = f.x + f.y;
        }
        {
            __half2 hs = __hmul2(e5lo(kq3.x), V.h[0]);
            hs = __hfma2(e5hi(kq3.x), V.h[1], hs); hs = __hfma2(e5lo(kq3.y), V.h[2], hs);
            hs = __hfma2(e5hi(kq3.y), V.h[3], hs); hs = __hfma2(e5lo(kq3.z), V.h[4], hs);
            hs = __hfma2(e5hi(kq3.z), V.h[5], hs); hs = __hfma2(e5lo(kq3.w), V.h[6], hs);
            hs = __hfma2(e5hi(kq3.w), V.h[7], hs);
            float2 f = __half22float2(hs); dotp[3] = f.x + f.y;
        }
#pragma unroll
        for (int r = 0; r < 4; r++) {
#pragma unroll
            for (int o = 16; o > 0; o >>= 1)
                dotp[r] += __shfl_xor_sync(0xffffffffu, dotp[r], o);
        }
        const int par = bt & 1;
        if (l == 0) {
#pragma unroll
            for (int r = 0; r < 4; r++) sdot[par * 64 + r * 16 + w] = dotp[r];
        }
        __syncthreads();

        // every warp redundantly reduces the 4x16 partials (no 2nd barrier)
        float v0 = sdot[par * 64 + l];          // rows rb+0 (l<16), rb+1 (l>=16)
        float v1 = sdot[par * 64 + 32 + l];     // rows rb+2, rb+3
#pragma unroll
        for (int o = 8; o > 0; o >>= 1) {
            v0 += __shfl_xor_sync(0xffffffffu, v0, o);
            v1 += __shfl_xor_sync(0xffffffffu, v1, o);
        }
        const int rb = r0 + bt * BATCH;
        const int my0 = rb + (l >> 4);
        const int my1 = rb + 2 + (l >> 4);
        float u0 = (my0 < r1) ? __fdividef(sa[my0 - r0], v0) : 0.f;
        float u1 = (my1 < r1) ? __fdividef(sa[my1 - r0], v1) : 0.f;
        if (t == 0 || t == 16) {
            if (my0 < r1) dU[my0] = u0;
            if (my1 < r1) dU[my1] = u1;
        }
        const float S31 = 2147483648.0f;
        __half2 uh0 = __float2half2_rn(__shfl_sync(0xffffffffu, u0, 0) * S31);
        __half2 uh1 = __float2half2_rn(__shfl_sync(0xffffffffu, u0, 16) * S31);
        __half2 uh2 = __float2half2_rn(__shfl_sync(0xffffffffu, u1, 0) * S31);
        __half2 uh3 = __float2half2_rn(__shfl_sync(0xffffffffu, u1, 16) * S31);

        // Phase B: colAcc partials += K^T u (reuse kq regs)
        __half2 bacc[8];
#pragma unroll
        for (int i = 0; i < 8; i++) bacc[i] = __float2half2_rn(0.f);
        bacc[0] = __hfma2(e5lo(kq0.x), uh0, bacc[0]);
        bacc[1] = __hfma2(e5hi(kq0.x), uh0, bacc[1]);
        bacc[2] = __hfma2(e5lo(kq0.y), uh0, bacc[2]);
        bacc[3] = __hfma2(e5hi(kq0.y), uh0, bacc[3]);
        bacc[4] = __hfma2(e5lo(kq0.z), uh0, bacc[4]);
        bacc[5] = __hfma2(e5hi(kq0.z), uh0, bacc[5]);
        bacc[6] = __hfma2(e5lo(kq0.w), uh0, bacc[6]);
        bacc[7] = __hfma2(e5hi(kq0.w), uh0, bacc[7]);
        bacc[0] = __hfma2(e5lo(kq1.x), uh1, bacc[0]);
        bacc[1] = __hfma2(e5hi(kq1.x), uh1, bacc[1]);
        bacc[2] = __hfma2(e5lo(kq1.y), uh1, bacc[2]);
        bacc[3] = __hfma2(e5hi(kq1.y), uh1, bacc[3]);
        bacc[4] = __hfma2(e5lo(kq1.z), uh1, bacc[4]);
        bacc[5] = __hfma2(e5hi(kq1.z), uh1, bacc[5]);
        bacc[6] = __hfma2(e5lo(kq1.w), uh1, bacc[6]);
        bacc[7] = __hfma2(e5hi(kq1.w), uh1, bacc[7]);
        bacc[0] = __hfma2(e5lo(kq2.x), uh2, bacc[0]);
        bacc[1] = __hfma2(e5hi(kq2.x), uh2, bacc[1]);
        bacc[2] = __hfma2(e5lo(kq2.y), uh2, bacc[2]);
        bacc[3] = __hfma2(e5hi(kq2.y), uh2, bacc[3]);
        bacc[4] = __hfma2(e5lo(kq2.z), uh2, bacc[4]);
        bacc[5] = __hfma2(e5hi(kq2.z), uh2, bacc[5]);
        bacc[6] = __hfma2(e5lo(kq2.w), uh2, bacc[6]);
        bacc[7] = __hfma2(e5hi(kq2.w), uh2, bacc[7]);
        bacc[0] = __hfma2(e5lo(kq3.x), uh3, bacc[0]);
        bacc[1] = __hfma2(e5hi(kq3.x), uh3, bacc[1]);
        bacc[2] = __hfma2(e5lo(kq3.y), uh3, bacc[2]);
        bacc[3] = __hfma2(e5hi(kq3.y), uh3, bacc[3]);
        bacc[4] = __hfma2(e5lo(kq3.z), uh3, bacc[4]);
        bacc[5] = __hfma2(e5hi(kq3.z), uh3, bacc[5]);
        bacc[6] = __hfma2(e5lo(kq3.w), uh3, bacc[6]);
        bacc[7] = __hfma2(e5hi(kq3.w), uh3, bacc[7]);
#pragma unroll
        for (int i = 0; i < 8; i++) {
            float2 f = __half22float2(bacc[i]);
            facc[2 * i]     += f.x;
            facc[2 * i + 1] += f.y;
        }
    }

    float4* outp = reinterpret_cast<float4*>(&dScr[bid][c0]);
#pragma unroll
    for (int i = 0; i < 4; i++)
        outp[i] = make_float4(facc[4 * i], facc[4 * i + 1],
                              facc[4 * i + 2], facc[4 * i + 3]);
}

// Sum the 148 per-block partials per column (4-way split, coalesced);
// produce colAcc and next v (half, *2^-8).
__global__ void __launch_bounds__(512) finalize_iter(const float* __restrict__ b, int iter) {
    __shared__ float sred[512];
    const int l7 = threadIdx.x & 127;
    const int q = threadIdx.x >> 7;         // 0..3, 148 = 4*37
    const int c = blockIdx.x * 128 + l7;
    float s = 0.f;
#pragma unroll
    for (int p = 0; p < 37; p++) s += dScr[q * 37 + p][c];
    sred[threadIdx.x] = s;
    __syncthreads();
    if (threadIdx.x < 128) {
        float tot = (sred[l7] + sred[l7 + 128]) + (sred[l7 + 256] + sred[l7 + 384]);
        tot *= (1.0f / 2147483648.0f);       // undo 2^31 u scale
        dColAccLast[c] = tot;
        dVh[(size_t)(iter + 1) * NN + c] =
            __float2half(__fdividef(b[c], tot) * 0.00390625f);
    }
}

// loss = -( dot(target,M)/eps + sum_i R_i ln u_i + sum_j C_j ln v_j )
__global__ void loss_kernel(const float* __restrict__ b, float* __restrict__ out) {
    __shared__ float sred[1024];
    float p = 0.f;
    for (int i = threadIdx.x; i < NN; i += 1024) {
        p += dR[i] * logf(dU[i]);
        p += dCs[i] * (logf(b[i]) - logf(dColAccLast[i]));
    }
    sred[threadIdx.x] = p;
    __syncthreads();
    for (int off = 512; off > 0; off >>= 1) {
        if (threadIdx.x < off) sred[threadIdx.x] += sred[threadIdx.x + off];
        __syncthreads();
    }
    if (threadIdx.x == 0) out[0] = -(sred[0] + dDot * (1.0f / EPSI));
}

extern "C" void kernel_launch(void* const* d_in, const int* in_sizes, int n_in,
                              void* d_out, int out_size) {
    const float* M = (const float*)d_in[0];
    const float* T = (const float*)d_in[1];
    const float* a = (const float*)d_in[2];
    const float* b = (const float*)d_in[3];
    float* out = (float*)d_out;

    static int smem_set = 0;
    if (!smem_set) {
        cudaFuncSetAttribute(fused_iter, cudaFuncAttributeMaxDynamicSharedMemorySize, SMEMSZ);
        smem_set = 1;
    }

    init_kernel<<<(NN + 255) / 256, 256>>>();
    prep_kernel<<<dim3(32, 32), 256>>>(M, T);
    for (int k = 0; k < NITERS; k++) {
        fused_iter<<<NBLK, THREADS, SMEMSZ>>>(a, k);
        finalize_iter<<<NN / 128, 512>>>(b, k);
    }
    loss_kernel<<<1, 1024>>>(b, out);
}

// round 8
// speedup vs baseline: 1.9450x; 1.1023x over previous
#include <cuda_runtime.h>
#include <cuda_fp16.h>
#include <cuda_fp8.h>

#define NN 8192
#define EPSI 0.1f
#define NITERS 50
#define NBLK 148            // one block per SM
#define THREADS 512
#define BATCH 8             // rows per pipeline stage
#define STAGES 2
#define NBATCH 7            // 56 rows per block max (pad with duplicate row, u=0)
#define STAGE_BYTES (BATCH * NN)   // 65536
#define SMEMSZ (STAGES * STAGE_BYTES + 64 * 4 + 2 * 128 * 4)

// K = exp(M/eps) as e5m2 fp8 (range [1, 22026.5] fits; decode = byte<<8 == fp16). 64MB.
__device__ __align__(16) unsigned char dK8[(size_t)NN * NN];
__device__ float dU[NN];                                 // true u of current iteration
__device__ __align__(16) __half dVh[(NITERS + 1) * NN];  // v * 2^-8 per iteration
__device__ __align__(16) float dScr[NBLK][NN];           // per-block colAcc partials (x 2^31)
__device__ float dColAccLast[NN];
__device__ float dR[NN];                                 // row sums of target
__device__ float dCs[NN];                                // col sums of target
__device__ float dDot;                                   // sum(target * M)

__device__ __forceinline__ __half2 e5lo(unsigned int x) {
    unsigned int r = __byte_perm(x, 0u, 0x1404);
    return *reinterpret_cast<__half2*>(&r);
}
__device__ __forceinline__ __half2 e5hi(unsigned int x) {
    unsigned int r = __byte_perm(x, 0u, 0x3424);
    return *reinterpret_cast<__half2*>(&r);
}
__device__ __forceinline__ unsigned long long pol_last() {
    unsigned long long p;
    asm("createpolicy.fractional.L2::evict_last.b64 %0, 1.0;" : "=l"(p));
    return p;
}
__device__ __forceinline__ unsigned long long pol_first() {
    unsigned long long p;
    asm("createpolicy.fractional.L2::evict_first.b64 %0, 1.0;" : "=l"(p));
    return p;
}
__device__ __forceinline__ void stK(unsigned char* p, uint2 v, unsigned long long pol) {
    asm volatile("st.global.L2::cache_hint.v2.u32 [%0], {%1,%2}, %3;"
                 :: "l"(p), "r"(v.x), "r"(v.y), "l"(pol) : "memory");
}
__device__ __forceinline__ float4 ldS(const float* p, unsigned long long pol) {
    float4 v;
    asm volatile("ld.global.nc.L2::cache_hint.v4.f32 {%0,%1,%2,%3}, [%4], %5;"
                 : "=f"(v.x), "=f"(v.y), "=f"(v.z), "=f"(v.w) : "l"(p), "l"(pol));
    return v;
}
// plain cp.async (the cache-hinted LDGSTS variant traps on sm_103a)
__device__ __forceinline__ void cpK(unsigned int dst, const unsigned char* src) {
    asm volatile("cp.async.cg.shared.global [%0], [%1], 16;"
                 :: "r"(dst), "l"(src) : "memory");
}

__global__ void init_kernel() {
    int j = blockIdx.x * blockDim.x + threadIdx.x;
    if (j < NN) {
        dR[j] = 0.f;
        dCs[j] = 0.f;
        dVh[j] = __float2half(0.00390625f);      // v_0 = 1, stored *2^-8
    }
    if (j == 0) dDot = 0.f;
}

// One pass over M and target: build K (e5m2), row/col sums of target, dot(target, M).
__global__ void __launch_bounds__(256) prep_kernel(const float* __restrict__ M,
                                                   const float* __restrict__ T) {
    __shared__ float sred[8 * 256];
    __shared__ float sdot_s[256];
    const unsigned long long pF = pol_first();
    const unsigned long long pL = pol_last();
    const int w = threadIdx.x >> 5, l = threadIdx.x & 31;
    const int col0 = blockIdx.x * 256 + l * 8;
    const int r0 = blockIdx.y * 256;
    const float SC = 10.0f * 1.4426950408889634f;

    float cs[8];
#pragma unroll
    for (int k = 0; k < 8; k++) cs[k] = 0.f;
    float dot = 0.f;

    for (int r = r0 + w; r < r0 + 256; r += 8) {
        size_t base = (size_t)r * NN + col0;
        float4 m0 = ldS(M + base, pF);
        float4 m1 = ldS(M + base + 4, pF);
        float4 t0 = ldS(T + base, pF);
        float4 t1 = ldS(T + base + 4, pF);

        union { uint2 u; __nv_fp8x2_storage_t s[4]; } P;
        P.s[0] = __nv_cvt_float2_to_fp8x2(make_float2(exp2f(m0.x * SC), exp2f(m0.y * SC)),
                                          __NV_SATFINITE, __NV_E5M2);
        P.s[1] = __nv_cvt_float2_to_fp8x2(make_float2(exp2f(m0.z * SC), exp2f(m0.w * SC)),
                                          __NV_SATFINITE, __NV_E5M2);
        P.s[2] = __nv_cvt_float2_to_fp8x2(make_float2(exp2f(m1.x * SC), exp2f(m1.y * SC)),
                                          __NV_SATFINITE, __NV_E5M2);
        P.s[3] = __nv_cvt_float2_to_fp8x2(make_float2(exp2f(m1.z * SC), exp2f(m1.w * SC)),
                                          __NV_SATFINITE, __NV_E5M2);
        stK(dK8 + base, P.u, pL);

        cs[0] += t0.x; cs[1] += t0.y; cs[2] += t0.z; cs[3] += t0.w;
        cs[4] += t1.x; cs[5] += t1.y; cs[6] += t1.z; cs[7] += t1.w;

        dot += m0.x * t0.x + m0.y * t0.y + m0.z * t0.z + m0.w * t0.w
             + m1.x * t1.x + m1.y * t1.y + m1.z * t1.z + m1.w * t1.w;

        float rs = t0.x + t0.y + t0.z + t0.w + t1.x + t1.y + t1.z + t1.w;
#pragma unroll
        for (int o = 16; o > 0; o >>= 1) rs += __shfl_xor_sync(0xffffffffu, rs, o);
        if (l == 0) atomicAdd(&dR[r], rs);
    }

#pragma unroll
    for (int k = 0; k < 8; k++) sred[w * 256 + l * 8 + k] = cs[k];
    sdot_s[threadIdx.x] = dot;
    __syncthreads();

    float s = 0.f;
#pragma unroll
    for (int w2 = 0; w2 < 8; w2++) s += sred[w2 * 256 + threadIdx.x];
    atomicAdd(&dCs[blockIdx.x * 256 + threadIdx.x], s);

    for (int off = 128; off > 0; off >>= 1) {
        if (threadIdx.x < off) sdot_s[threadIdx.x] += sdot_s[threadIdx.x + off];
        __syncthreads();
    }
    if (threadIdx.x == 0) atomicAdd(&dDot, sdot_s[0]);
}

// Fused Sinkhorn pair: one sweep over K computes u_i = a_i/(K_i.v) AND colAcc
// partials. 148 blocks (1/SM), 512 threads, thread owns 16 fixed columns.
// K staged through smem with a 2-deep cp.async pipeline (8 rows x 64KB/stage);
// one __syncthreads per 8-row batch (7 per iteration).
__global__ void __launch_bounds__(THREADS, 1)
fused_iter(const float* __restrict__ a, int iter) {
    extern __shared__ char smem[];
    float* sa   = reinterpret_cast<float*>(smem + STAGES * STAGE_BYTES);   // [64]
    float* sdot = sa + 64;                                                 // [2][128]
    const int t = threadIdx.x;
    const int l = t & 31;
    const int w = t >> 5;
    const int c0 = t * 16;
    const int bid = blockIdx.x;
    const int r0 = (bid * NN) / NBLK;
    const int r1 = ((bid + 1) * NN) / NBLK;   // 55 or 56 rows

    if (t < 64) {
        int rr = r0 + t;
        sa[t] = (rr < r1) ? a[rr] * 0.00390625f : 0.f;
    }

    union { uint4 q[2]; __half2 h[8]; } V;   // v*2^-8 for my 16 cols
    const uint4* vp = reinterpret_cast<const uint4*>(dVh + (size_t)iter * NN + c0);
    V.q[0] = vp[0];
    V.q[1] = vp[1];

    float facc[16];
#pragma unroll
    for (int i = 0; i < 16; i++) facc[i] = 0.f;

    // prologue: fill both stages
#pragma unroll
    for (int s = 0; s < STAGES; s++) {
        int rb = r0 + s * BATCH;
#pragma unroll
        for (int r = 0; r < BATCH; r++) {
            int gr = rb + r; gr = (gr < r1) ? gr : (r1 - 1);
            unsigned int dst = (unsigned int)__cvta_generic_to_shared(
                smem + s * STAGE_BYTES + r * NN + c0);
            cpK(dst, dK8 + (size_t)gr * NN + c0);
        }
        asm volatile("cp.async.commit_group;" ::: "memory");
    }

#pragma unroll 1
    for (int bt = 0; bt < NBATCH; bt++) {
        asm volatile("cp.async.wait_group 1;" ::: "memory");
        const uint4* sp = reinterpret_cast<const uint4*>(
            smem + (bt & 1) * STAGE_BYTES) + t;
        uint4 kq[BATCH];
#pragma unroll
        for (int r = 0; r < BATCH; r++) kq[r] = sp[r * 512];

        // refill just-freed stage (data already in regs)
        int nb = bt + STAGES;
        if (nb < NBATCH) {
            int rb = r0 + nb * BATCH;
#pragma unroll
            for (int r = 0; r < BATCH; r++) {
                int gr = rb + r; gr = (gr < r1) ? gr : (r1 - 1);
                unsigned int dst = (unsigned int)__cvta_generic_to_shared(
                    smem + (nb & 1) * STAGE_BYTES + r * NN + c0);
                cpK(dst, dK8 + (size_t)gr * NN + c0);
            }
        }
        asm volatile("cp.async.commit_group;" ::: "memory");

        // Phase A: per-row partial dots with v
        float dotp[BATCH];
#pragma unroll
        for (int r = 0; r < BATCH; r++) {
            __half2 hs = __hmul2(e5lo(kq[r].x), V.h[0]);
            hs = __hfma2(e5hi(kq[r].x), V.h[1], hs);
            hs = __hfma2(e5lo(kq[r].y), V.h[2], hs);
            hs = __hfma2(e5hi(kq[r].y), V.h[3], hs);
            hs = __hfma2(e5lo(kq[r].z), V.h[4], hs);
            hs = __hfma2(e5hi(kq[r].z), V.h[5], hs);
            hs = __hfma2(e5lo(kq[r].w), V.h[6], hs);
            hs = __hfma2(e5hi(kq[r].w), V.h[7], hs);
            float2 f = __half22float2(hs);
            dotp[r] = f.x + f.y;
        }
#pragma unroll
        for (int r = 0; r < BATCH; r++) {
#pragma unroll
            for (int o = 16; o > 0; o >>= 1)
                dotp[r] += __shfl_xor_sync(0xffffffffu, dotp[r], o);
        }
        const int par = bt & 1;
        if (l == 0) {
#pragma unroll
            for (int r = 0; r < BATCH; r++) sdot[par * 128 + r * 16 + w] = dotp[r];
        }
        __syncthreads();

        // every warp redundantly reduces the 8x16 partials (no 2nd barrier)
        float x0 = sdot[par * 128 + l];          // rows 0,1
        float x1 = sdot[par * 128 + 32 + l];     // rows 2,3
        float x2 = sdot[par * 128 + 64 + l];     // rows 4,5
        float x3 = sdot[par * 128 + 96 + l];     // rows 6,7
#pragma unroll
        for (int o = 8; o > 0; o >>= 1) {
            x0 += __shfl_xor_sync(0xffffffffu, x0, o);
            x1 += __shfl_xor_sync(0xffffffffu, x1, o);
            x2 += __shfl_xor_sync(0xffffffffu, x2, o);
            x3 += __shfl_xor_sync(0xffffffffu, x3, o);
        }
        const int rb = r0 + bt * BATCH;
        const int half16 = l >> 4;                    // 0 or 1
        const int my0 = rb + 0 + half16;
        const int my1 = rb + 2 + half16;
        const int my2 = rb + 4 + half16;
        const int my3 = rb + 6 + half16;
        float u0 = (my0 < r1) ? __fdividef(sa[my0 - r0], x0) : 0.f;
        float u1 = (my1 < r1) ? __fdividef(sa[my1 - r0], x1) : 0.f;
        float u2 = (my2 < r1) ? __fdividef(sa[my2 - r0], x2) : 0.f;
        float u3 = (my3 < r1) ? __fdividef(sa[my3 - r0], x3) : 0.f;
        if (t == 0 || t == 16) {
            if (my0 < r1) dU[my0] = u0;
            if (my1 < r1) dU[my1] = u1;
            if (my2 < r1) dU[my2] = u2;
            if (my3 < r1) dU[my3] = u3;
        }
        const float S31 = 2147483648.0f;
        __half2 uh[BATCH];
        uh[0] = __float2half2_rn(__shfl_sync(0xffffffffu, u0, 0) * S31);
        uh[1] = __float2half2_rn(__shfl_sync(0xffffffffu, u0, 16) * S31);
        uh[2] = __float2half2_rn(__shfl_sync(0xffffffffu, u1, 0) * S31);
        uh[3] = __float2half2_rn(__shfl_sync(0xffffffffu, u1, 16) * S31);
        uh[4] = __float2half2_rn(__shfl_sync(0xffffffffu, u2, 0) * S31);
        uh[5] = __float2half2_rn(__shfl_sync(0xffffffffu, u2, 16) * S31);
        uh[6] = __float2half2_rn(__shfl_sync(0xffffffffu, u3, 0) * S31);
        uh[7] = __float2half2_rn(__shfl_sync(0xffffffffu, u3, 16) * S31);

        // Phase B: colAcc partials += K^T u (reuse kq regs)
        __half2 bacc[8];
#pragma unroll
        for (int i = 0; i < 8; i++) bacc[i] = __float2half2_rn(0.f);
#pragma unroll
        for (int r = 0; r < BATCH; r++) {
            bacc[0] = __hfma2(e5lo(kq[r].x), uh[r], bacc[0]);
            bacc[1] = __hfma2(e5hi(kq[r].x), uh[r], bacc[1]);
            bacc[2] = __hfma2(e5lo(kq[r].y), uh[r], bacc[2]);
            bacc[3] = __hfma2(e5hi(kq[r].y), uh[r], bacc[3]);
            bacc[4] = __hfma2(e5lo(kq[r].z), uh[r], bacc[4]);
            bacc[5] = __hfma2(e5hi(kq[r].z), uh[r], bacc[5]);
            bacc[6] = __hfma2(e5lo(kq[r].w), uh[r], bacc[6]);
            bacc[7] = __hfma2(e5hi(kq[r].w), uh[r], bacc[7]);
        }
#pragma unroll
        for (int i = 0; i < 8; i++) {
            float2 f = __half22float2(bacc[i]);
            facc[2 * i]     += f.x;
            facc[2 * i + 1] += f.y;
        }
    }

    float4* outp = reinterpret_cast<float4*>(&dScr[bid][c0]);
#pragma unroll
    for (int i = 0; i < 4; i++)
        outp[i] = make_float4(facc[4 * i], facc[4 * i + 1],
                              facc[4 * i + 2], facc[4 * i + 3]);
}

// Sum the 148 per-block partials per column (8-way split, coalesced);
// produce colAcc and next v (half, *2^-8). 128 blocks x 512 threads.
__global__ void __launch_bounds__(512) finalize_iter(const float* __restrict__ b, int iter) {
    __shared__ float sred[512];
    const int l6 = threadIdx.x & 63;
    const int g = threadIdx.x >> 6;          // 0..7, rows g*19 .. min(g*19+18, 147)
    const int c = blockIdx.x * 64 + l6;
    const int p0 = g * 19;
    const int p1 = min(p0 + 19, NBLK);
    float s = 0.f;
    for (int p = p0; p < p1; p++) s += dScr[p][c];
    sred[threadIdx.x] = s;
    __syncthreads();
    if (threadIdx.x < 64) {
        float tot = 0.f;
#pragma unroll
        for (int g2 = 0; g2 < 8; g2++) tot += sred[g2 * 64 + l6];
        tot *= (1.0f / 2147483648.0f);       // undo 2^31 u scale
        dColAccLast[c] = tot;
        dVh[(size_t)(iter + 1) * NN + c] =
            __float2half(__fdividef(b[c], tot) * 0.00390625f);
    }
}

// loss = -( dot(target,M)/eps + sum_i R_i ln u_i + sum_j C_j ln v_j )
__global__ void loss_kernel(const float* __restrict__ b, float* __restrict__ out) {
    __shared__ float sred[1024];
    float p = 0.f;
    for (int i = threadIdx.x; i < NN; i += 1024) {
        p += dR[i] * logf(dU[i]);
        p += dCs[i] * (logf(b[i]) - logf(dColAccLast[i]));
    }
    sred[threadIdx.x] = p;
    __syncthreads();
    for (int off = 512; off > 0; off >>= 1) {
        if (threadIdx.x < off) sred[threadIdx.x] += sred[threadIdx.x + off];
        __syncthreads();
    }
    if (threadIdx.x == 0) out[0] = -(sred[0] + dDot * (1.0f / EPSI));
}

extern "C" void kernel_launch(void* const* d_in, const int* in_sizes, int n_in,
                              void* d_out, int out_size) {
    const float* M = (const float*)d_in[0];
    const float* T = (const float*)d_in[1];
    const float* a = (const float*)d_in[2];
    const float* b = (const float*)d_in[3];
    float* out = (float*)d_out;

    static int smem_set = 0;
    if (!smem_set) {
        cudaFuncSetAttribute(fused_iter, cudaFuncAttributeMaxDynamicSharedMemorySize, SMEMSZ);
        smem_set = 1;
    }

    init_kernel<<<(NN + 255) / 256, 256>>>();
    prep_kernel<<<dim3(32, 32), 256>>>(M, T);
    for (int k = 0; k < NITERS; k++) {
        fused_iter<<<NBLK, THREADS, SMEMSZ>>>(a, k);
        finalize_iter<<<NN / 64, 512>>>(b, k);
    }
    loss_kernel<<<1, 1024>>>(b, out);
}